// round 9
// baseline (speedup 1.0000x reference)
#include <cuda_runtime.h>
#include <math.h>

#define B    8
#define V    32000
#define S    512
#define NCH  111          // V-chunks: grid = 111*8 = 888 = 6*148 (perfect SM balance)
#define BSN  (B * S)      // 4096 (b,s) columns
#define P    (S - 4)      // 508 n-gram windows
#define MSPL 32           // mask splits per batch
#define MW   (S / MSPL)   // 16 mask outputs per block

// -------- scratch (device globals; no allocation allowed) --------
// g_best[bs] = (monotonic_key(max) << 32) | ~argmax_token.
// Zero is the identity for max over finite floats; k_lse re-zeroes
// it (after k_mask has consumed it) for the next graph replay.
__device__ unsigned long long g_best[BSN];
__device__ float g_gm  [BSN];         // global max (float), written by k_mask
__device__ int   g_list[BSN];         // worklist of masked bs
__device__ int   g_nlist;             // worklist length
__device__ float g_acc;               // accumulated masked penalty

// order-preserving float -> uint32 (exact)
__device__ __forceinline__ unsigned int fkey(float f)
{
    unsigned int u = __float_as_uint(f);
    return u ^ ((unsigned int)(((int)u) >> 31) | 0x80000000u);
}
__device__ __forceinline__ float funkey(unsigned int k)
{
    unsigned int u = (k & 0x80000000u) ? (k ^ 0x80000000u) : ~k;
    return __uint_as_float(u);
}

// ================================================================
// Kernel 1: streaming argmax over balanced contiguous V-ranges +
// packed-u64 RED.MAX merge. grid = (111, 8) = 888 blocks (6/SM),
// 128 thr; thread owns 4 consecutive s via float4 streaming loads.
// ================================================================
__global__ __launch_bounds__(128) void k_argmax(const float* __restrict__ pred)
{
    const int q = blockIdx.x;
    const int b = blockIdx.y;
    const int t = threadIdx.x;
    const int s0 = t * 4;

    if (q == 0 && b == 0 && t == 0) { g_nlist = 0; g_acc = 0.0f; }

    const int vStart = (q * V) / NCH;          // balanced split: 288/289 rows
    const int vEnd   = ((q + 1) * V) / NCH;

    const float4* p = reinterpret_cast<const float4*>(
        pred + (size_t)(b * V + vStart) * S + s0);
    const int pstep = S / 4;

    float m0 = -INFINITY, m1 = -INFINITY, m2 = -INFINITY, m3 = -INFINITY;
    int   i0 = 0, i1 = 0, i2 = 0, i3 = 0;

#pragma unroll 8
    for (int v = vStart; v < vEnd; v++) {
        float4 x = __ldcs(p);          // streaming: evict-first
        p += pstep;
        // strict '>' + ascending v => first occurrence on exact ties
        if (x.x > m0) { m0 = x.x; i0 = v; }
        if (x.y > m1) { m1 = x.y; i1 = v; }
        if (x.z > m2) { m2 = x.z; i2 = v; }
        if (x.w > m3) { m3 = x.w; i3 = v; }
    }

    // pack + no-return atomic max merge (ties -> smaller token wins)
    const int bs = b * S + s0;
    atomicMax(&g_best[bs + 0],
        ((unsigned long long)fkey(m0) << 32) | (unsigned int)(~i0));
    atomicMax(&g_best[bs + 1],
        ((unsigned long long)fkey(m1) << 32) | (unsigned int)(~i1));
    atomicMax(&g_best[bs + 2],
        ((unsigned long long)fkey(m2) << 32) | (unsigned int)(~i2));
    atomicMax(&g_best[bs + 3],
        ((unsigned long long)fkey(m3) << 32) | (unsigned int)(~i3));
}

// ================================================================
// Kernel 2: 4-gram repeat mask + worklist compaction + g_gm export.
// grid = (MSPL, B) = 256 blocks of 256 (8 warps). Block x of batch
// b builds all keys in smem from g_best tokens, computes rep for
// its 19-position window [p0-3, p0+MW), emits mask for [p0, p0+MW).
// ================================================================
__global__ __launch_bounds__(256) void k_mask()
{
    const int b    = blockIdx.y;
    const int p0   = blockIdx.x * MW;
    const int t    = threadIdx.x;
    const int w    = t >> 5;            // warp 0..7
    const int lane = t & 31;

    __shared__ int                tok[S];
    __shared__ unsigned long long key[S];       // P used
    __shared__ unsigned char      rep[MW + 4];

    // tokens from packed best (low 32 bits = ~token)
    unsigned long long be0 = g_best[b * S + t];
    unsigned long long be1 = g_best[b * S + t + 256];
    tok[t]       = (int)(~(unsigned int)be0);
    tok[t + 256] = (int)(~(unsigned int)be1);
    if (t < MW + 4) rep[t] = 0;
    __syncthreads();

    // export float max for this block's owned positions (duplicate-
    // safe: every block writes identical values; only owned range
    // is needed, but writing two strided entries per thread is free)
    if (blockIdx.x == 0) {
        g_gm[b * S + t]       = funkey((unsigned int)(be0 >> 32));
        g_gm[b * S + t + 256] = funkey((unsigned int)(be1 >> 32));
    }

    // packed 4-gram keys (tokens < 32000 < 2^15 -> 60 bits)
#pragma unroll
    for (int tt = t; tt < P; tt += 256) {
        key[tt] = ((unsigned long long)tok[tt]     << 45)
                | ((unsigned long long)tok[tt + 1] << 30)
                | ((unsigned long long)tok[tt + 2] << 15)
                |  (unsigned long long)tok[tt + 3];
    }
    __syncthreads();

    // warp-parallel duplicate scan: warp w covers li = w, w+8, w+16
#pragma unroll
    for (int r = 0; r < 3; r++) {
        int li  = w + 8 * r;            // 0..23; need 0..MW+2
        int pos = p0 - 3 + li;
        if (li < MW + 3 && pos >= 0 && pos < P) {
            unsigned long long k = key[pos];
            bool eq = false;
            int nIt = (pos + 31) >> 5;
            for (int it = 0; it < nIt; it++) {
                int j = lane + (it << 5);
                eq |= (j < pos) && (key[j] == k);
            }
            if (__any_sync(0xffffffffu, eq) && lane == 0) rep[li] = 1;
        }
    }
    __syncthreads();

    // mask outputs for positions [p0, p0+MW)
    if (t < MW) {
        int pos = p0 + t;
        int lo  = pos - 3 > 0 ? pos - 3 : 0;
        int hi  = pos < P - 1 ? pos : P - 1;
        int msk = 0;
        for (int q = lo; q <= hi; q++)
            msk |= rep[q - p0 + 3];

        if (msk) {
            int slot = atomicAdd(&g_nlist, 1);
            g_list[slot] = b * S + pos;
        }
    }
}

// ================================================================
// Kernel 3: exact logsumexp for worklisted columns + g_best reset.
// grid = 64 blocks of 128, grid-stride over the worklist.
// (g_best reset is safe here: k_mask has already consumed it.)
// ================================================================
__global__ __launch_bounds__(128) void k_lse(const float* __restrict__ pred)
{
    const int t = threadIdx.x;

    // reset g_best for next replay (64*128 = 8192 >= 4096)
    const int z = blockIdx.x * 128 + t;
    if (z < BSN) g_best[z] = 0ull;

    const int n = g_nlist;
    for (int w = blockIdx.x; w < n; w += 64) {
        const int bs = g_list[w];
        const int b = bs / S;
        const int s = bs % S;
        const float m = g_gm[bs];

        const float* p = pred + (size_t)b * V * S + s;

        float d = 0.0f;
        for (int v = t; v < V; v += 128)
            d += __expf(p[(size_t)v * S] - m);

        __shared__ float red[128];
        red[t] = d;
        __syncthreads();
        for (int st = 64; st > 0; st >>= 1) {
            if (t < st) red[t] += red[t + st];
            __syncthreads();
        }

        if (t == 0) {
            float D  = red[0];              // >= 1 (max term included)
            float lp = -logf(D);            // log_softmax at the argmax
            float pr = __expf(lp);
            float om = fmaxf(1.0f - pr, 1e-20f);
            atomicAdd(&g_acc, -logf(om));
        }
        __syncthreads();
    }
}

// ================================================================
// Kernel 4: final scalar.
// ================================================================
__global__ void k_final(float* __restrict__ out)
{
    if (threadIdx.x == 0) out[0] = g_acc / (float)B;
}

// ================================================================
extern "C" void kernel_launch(void* const* d_in, const int* in_sizes, int n_in,
                              void* d_out, int out_size)
{
    const float* pred = (const float*)d_in[0];

    dim3 g1(NCH, B);
    k_argmax<<<g1, 128>>>(pred);

    dim3 g2(MSPL, B);
    k_mask<<<g2, 256>>>();

    k_lse<<<64, 128>>>(pred);
    k_final<<<1, 32>>>((float*)d_out);
}

// round 10
// speedup vs baseline: 1.1125x; 1.1125x over previous
#include <cuda_runtime.h>
#include <math.h>

#define B    8
#define V    32000
#define S    512
#define NC   125          // chunks in argmax pass (measured-good config)
#define VC   (V / NC)     // 256 v per chunk (compile-time trip count!)
#define BSN  (B * S)      // 4096 (b,s) columns
#define P    (S - 4)      // 508 n-gram windows
#define MSPL 32           // mask splits per batch
#define MW   (S / MSPL)   // 16 mask outputs per block

// -------- scratch (device globals; no allocation allowed) --------
// g_best[bs] = (monotonic_key(max) << 32) | ~argmax_token.
// Zero is the identity for max over finite floats; k_lse re-zeroes
// it (after k_mask has consumed it) for the next graph replay.
__device__ unsigned long long g_best[BSN];
__device__ float g_gm  [BSN];         // global max (float), written by k_mask
__device__ int   g_list[BSN];         // worklist of masked bs
__device__ int   g_nlist;             // worklist length
__device__ float g_acc;               // accumulated masked penalty
__device__ int   g_done;              // k_lse completion counter

// order-preserving float -> uint32 (exact)
__device__ __forceinline__ unsigned int fkey(float f)
{
    unsigned int u = __float_as_uint(f);
    return u ^ ((unsigned int)(((int)u) >> 31) | 0x80000000u);
}
__device__ __forceinline__ float funkey(unsigned int k)
{
    unsigned int u = (k & 0x80000000u) ? (k ^ 0x80000000u) : ~k;
    return __uint_as_float(u);
}

// ================================================================
// Kernel 1: streaming argmax per V-chunk + packed-u64 RED.MAX merge.
// grid = (125, 8) = 1000 blocks, 128 thr; thread owns 4 consecutive
// s via float4 streaming loads. (R8 measured-good config.)
// ================================================================
__global__ __launch_bounds__(128) void k_argmax(const float* __restrict__ pred)
{
    const int c = blockIdx.x;
    const int b = blockIdx.y;
    const int t = threadIdx.x;
    const int s0 = t * 4;

    if (c == 0 && b == 0 && t == 0) { g_nlist = 0; g_acc = 0.0f; }

    const float4* p = reinterpret_cast<const float4*>(
        pred + (size_t)(b * V + c * VC) * S + s0);
    const int pstep = S / 4;

    float m0 = -INFINITY, m1 = -INFINITY, m2 = -INFINITY, m3 = -INFINITY;
    int   i0 = 0, i1 = 0, i2 = 0, i3 = 0;

    int v = c * VC;
#pragma unroll 8
    for (int vv = 0; vv < VC; vv++, v++) {
        float4 x = __ldcs(p);          // streaming: evict-first
        p += pstep;
        // strict '>' + ascending v => first occurrence on exact ties
        if (x.x > m0) { m0 = x.x; i0 = v; }
        if (x.y > m1) { m1 = x.y; i1 = v; }
        if (x.z > m2) { m2 = x.z; i2 = v; }
        if (x.w > m3) { m3 = x.w; i3 = v; }
    }

    // pack + no-return atomic max merge (ties -> smaller token wins)
    const int bs = b * S + s0;
    atomicMax(&g_best[bs + 0],
        ((unsigned long long)fkey(m0) << 32) | (unsigned int)(~i0));
    atomicMax(&g_best[bs + 1],
        ((unsigned long long)fkey(m1) << 32) | (unsigned int)(~i1));
    atomicMax(&g_best[bs + 2],
        ((unsigned long long)fkey(m2) << 32) | (unsigned int)(~i2));
    atomicMax(&g_best[bs + 3],
        ((unsigned long long)fkey(m3) << 32) | (unsigned int)(~i3));
}

// ================================================================
// Kernel 2: 4-gram repeat mask + worklist compaction + g_gm export.
// grid = (MSPL, B) = 256 blocks of 256 (8 warps). Block x of batch
// b builds all keys in smem from g_best tokens, computes rep for
// its 19-position window [p0-3, p0+MW), emits mask for [p0, p0+MW).
// ================================================================
__global__ __launch_bounds__(256) void k_mask()
{
    const int b    = blockIdx.y;
    const int p0   = blockIdx.x * MW;
    const int t    = threadIdx.x;
    const int w    = t >> 5;            // warp 0..7
    const int lane = t & 31;

    __shared__ int                tok[S];
    __shared__ unsigned long long key[S];       // P used
    __shared__ unsigned char      rep[MW + 4];

    // tokens from packed best (low 32 bits = ~token)
    unsigned long long be0 = g_best[b * S + t];
    unsigned long long be1 = g_best[b * S + t + 256];
    tok[t]       = (int)(~(unsigned int)be0);
    tok[t + 256] = (int)(~(unsigned int)be1);
    if (t < MW + 4) rep[t] = 0;
    __syncthreads();

    // export float max (block 0 of each batch only; duplicate-safe)
    if (blockIdx.x == 0) {
        g_gm[b * S + t]       = funkey((unsigned int)(be0 >> 32));
        g_gm[b * S + t + 256] = funkey((unsigned int)(be1 >> 32));
    }

    // packed 4-gram keys (tokens < 32000 < 2^15 -> 60 bits)
#pragma unroll
    for (int tt = t; tt < P; tt += 256) {
        key[tt] = ((unsigned long long)tok[tt]     << 45)
                | ((unsigned long long)tok[tt + 1] << 30)
                | ((unsigned long long)tok[tt + 2] << 15)
                |  (unsigned long long)tok[tt + 3];
    }
    __syncthreads();

    // warp-parallel duplicate scan: warp w covers li = w, w+8, w+16
#pragma unroll
    for (int r = 0; r < 3; r++) {
        int li  = w + 8 * r;            // 0..23; need 0..MW+2
        int pos = p0 - 3 + li;
        if (li < MW + 3 && pos >= 0 && pos < P) {
            unsigned long long k = key[pos];
            bool eq = false;
            int nIt = (pos + 31) >> 5;
            for (int it = 0; it < nIt; it++) {
                int j = lane + (it << 5);
                eq |= (j < pos) && (key[j] == k);
            }
            if (__any_sync(0xffffffffu, eq) && lane == 0) rep[li] = 1;
        }
    }
    __syncthreads();

    // mask outputs for positions [p0, p0+MW)
    if (t < MW) {
        int pos = p0 + t;
        int lo  = pos - 3 > 0 ? pos - 3 : 0;
        int hi  = pos < P - 1 ? pos : P - 1;
        int msk = 0;
        for (int q = lo; q <= hi; q++)
            msk |= rep[q - p0 + 3];

        if (msk) {
            int slot = atomicAdd(&g_nlist, 1);
            g_list[slot] = b * S + pos;
        }
    }
}

// ================================================================
// Kernel 3: exact logsumexp for worklisted columns + g_best reset +
// final scalar via last-block-done (no separate k_final launch).
// grid = 64 blocks of 128, grid-stride over the worklist.
// ================================================================
__global__ __launch_bounds__(128) void k_lse(const float* __restrict__ pred,
                                             float* __restrict__ out)
{
    const int t = threadIdx.x;

    // reset g_best for next replay (64*128 = 8192 >= 4096)
    const int z = blockIdx.x * 128 + t;
    if (z < BSN) g_best[z] = 0ull;

    const int n = g_nlist;
    for (int w = blockIdx.x; w < n; w += 64) {
        const int bs = g_list[w];
        const int b = bs / S;
        const int s = bs % S;
        const float m = g_gm[bs];

        const float* p = pred + (size_t)b * V * S + s;

        float d = 0.0f;
        for (int v = t; v < V; v += 128)
            d += __expf(p[(size_t)v * S] - m);

        __shared__ float red[128];
        red[t] = d;
        __syncthreads();
        for (int st = 64; st > 0; st >>= 1) {
            if (t < st) red[t] += red[t + st];
            __syncthreads();
        }

        if (t == 0) {
            float D  = red[0];              // >= 1 (max term included)
            float lp = -logf(D);            // log_softmax at the argmax
            float pr = __expf(lp);
            float om = fmaxf(1.0f - pr, 1e-20f);
            atomicAdd(&g_acc, -logf(om));
        }
        __syncthreads();
    }

    // last block to finish publishes the result and resets the counter
    if (t == 0) {
        __threadfence();
        if (atomicAdd(&g_done, 1) == 63) {
            out[0] = g_acc / (float)B;
            g_done = 0;
        }
    }
}

// ================================================================
extern "C" void kernel_launch(void* const* d_in, const int* in_sizes, int n_in,
                              void* d_out, int out_size)
{
    const float* pred = (const float*)d_in[0];

    dim3 g1(NC, B);
    k_argmax<<<g1, 128>>>(pred);

    dim3 g2(MSPL, B);
    k_mask<<<g2, 256>>>();

    k_lse<<<64, 128>>>(pred, (float*)d_out);
}

// round 11
// speedup vs baseline: 1.1162x; 1.0033x over previous
#include <cuda_runtime.h>
#include <math.h>

#define B    8
#define V    32000
#define S    512
#define NC   125          // chunks in argmax pass (measured-good config)
#define VC   (V / NC)     // 256 v per chunk (compile-time trip count)
#define BSN  (B * S)      // 4096 (b,s) columns
#define P    (S - 4)      // 508 n-gram windows
#define MSPL 32           // mask splits per batch
#define MW   (S / MSPL)   // 16 mask outputs per block
#define NBLK (MSPL * B)   // 256 mask blocks

// -------- scratch (device globals; no allocation allowed) --------
// g_best[bs] = (monotonic_key(max) << 32) | ~argmax_token.
// Zero is the identity for max over finite floats; the last mask
// block re-zeroes it for the next graph replay.
__device__ unsigned long long g_best[BSN];
__device__ float g_gm  [BSN];         // global max (float)
__device__ int   g_list[BSN];         // worklist of masked bs
__device__ int   g_nlist;             // worklist length
__device__ int   g_done;              // mask-block completion counter

// order-preserving float -> uint32 (exact)
__device__ __forceinline__ unsigned int fkey(float f)
{
    unsigned int u = __float_as_uint(f);
    return u ^ ((unsigned int)(((int)u) >> 31) | 0x80000000u);
}
__device__ __forceinline__ float funkey(unsigned int k)
{
    unsigned int u = (k & 0x80000000u) ? (k ^ 0x80000000u) : ~k;
    return __uint_as_float(u);
}

// ================================================================
// Kernel 1: streaming argmax per V-chunk + packed-u64 RED.MAX merge.
// grid = (125, 8) = 1000 blocks, 128 thr; thread owns 4 consecutive
// s via float4 streaming loads. Verified at the ~6.4 TB/s LTS cap.
// ================================================================
__global__ __launch_bounds__(128) void k_argmax(const float* __restrict__ pred)
{
    const int c = blockIdx.x;
    const int b = blockIdx.y;
    const int t = threadIdx.x;
    const int s0 = t * 4;

    if (c == 0 && b == 0 && t == 0) g_nlist = 0;

    const float4* p = reinterpret_cast<const float4*>(
        pred + (size_t)(b * V + c * VC) * S + s0);
    const int pstep = S / 4;

    float m0 = -INFINITY, m1 = -INFINITY, m2 = -INFINITY, m3 = -INFINITY;
    int   i0 = 0, i1 = 0, i2 = 0, i3 = 0;

    int v = c * VC;
#pragma unroll 8
    for (int vv = 0; vv < VC; vv++, v++) {
        float4 x = __ldcs(p);          // streaming: evict-first
        p += pstep;
        // strict '>' + ascending v => first occurrence on exact ties
        if (x.x > m0) { m0 = x.x; i0 = v; }
        if (x.y > m1) { m1 = x.y; i1 = v; }
        if (x.z > m2) { m2 = x.z; i2 = v; }
        if (x.w > m3) { m3 = x.w; i3 = v; }
    }

    // pack + no-return atomic max merge (ties -> smaller token wins)
    const int bs = b * S + s0;
    atomicMax(&g_best[bs + 0],
        ((unsigned long long)fkey(m0) << 32) | (unsigned int)(~i0));
    atomicMax(&g_best[bs + 1],
        ((unsigned long long)fkey(m1) << 32) | (unsigned int)(~i1));
    atomicMax(&g_best[bs + 2],
        ((unsigned long long)fkey(m2) << 32) | (unsigned int)(~i2));
    atomicMax(&g_best[bs + 3],
        ((unsigned long long)fkey(m3) << 32) | (unsigned int)(~i3));
}

// ================================================================
// Kernel 2: 4-gram repeat mask + worklist compaction, then the
// LAST block to finish processes the worklist (exact logsumexp
// penalty), resets scratch, and writes the output scalar.
// grid = (MSPL, B) = 256 blocks of 256 (8 warps).
// ================================================================
__global__ __launch_bounds__(256) void k_masklse(const float* __restrict__ pred,
                                                 float* __restrict__ out)
{
    const int b    = blockIdx.y;
    const int p0   = blockIdx.x * MW;
    const int t    = threadIdx.x;
    const int w    = t >> 5;            // warp 0..7
    const int lane = t & 31;

    __shared__ int                tok[S];
    __shared__ unsigned long long key[S];       // P used
    __shared__ unsigned char      rep[MW + 4];
    __shared__ int                isLast;
    __shared__ float              red[256];

    // tokens from packed best (low 32 bits = ~token)
    unsigned long long be0 = g_best[b * S + t];
    unsigned long long be1 = g_best[b * S + t + 256];
    tok[t]       = (int)(~(unsigned int)be0);
    tok[t + 256] = (int)(~(unsigned int)be1);
    if (t < MW + 4) rep[t] = 0;
    __syncthreads();

    // export float max (block 0 of each batch only; duplicate-safe)
    if (blockIdx.x == 0) {
        g_gm[b * S + t]       = funkey((unsigned int)(be0 >> 32));
        g_gm[b * S + t + 256] = funkey((unsigned int)(be1 >> 32));
    }

    // packed 4-gram keys (tokens < 32000 < 2^15 -> 60 bits)
#pragma unroll
    for (int tt = t; tt < P; tt += 256) {
        key[tt] = ((unsigned long long)tok[tt]     << 45)
                | ((unsigned long long)tok[tt + 1] << 30)
                | ((unsigned long long)tok[tt + 2] << 15)
                |  (unsigned long long)tok[tt + 3];
    }
    __syncthreads();

    // warp-parallel duplicate scan: warp w covers li = w, w+8, w+16
#pragma unroll
    for (int r = 0; r < 3; r++) {
        int li  = w + 8 * r;            // 0..23; need 0..MW+2
        int pos = p0 - 3 + li;
        if (li < MW + 3 && pos >= 0 && pos < P) {
            unsigned long long k = key[pos];
            bool eq = false;
            int nIt = (pos + 31) >> 5;
            for (int it = 0; it < nIt; it++) {
                int j = lane + (it << 5);
                eq |= (j < pos) && (key[j] == k);
            }
            if (__any_sync(0xffffffffu, eq) && lane == 0) rep[li] = 1;
        }
    }
    __syncthreads();

    // mask outputs for positions [p0, p0+MW)
    if (t < MW) {
        int pos = p0 + t;
        int lo  = pos - 3 > 0 ? pos - 3 : 0;
        int hi  = pos < P - 1 ? pos : P - 1;
        int msk = 0;
        for (int q = lo; q <= hi; q++)
            msk |= rep[q - p0 + 3];

        if (msk) {
            int slot = atomicAdd(&g_nlist, 1);
            g_list[slot] = b * S + pos;
        }
    }

    // ---- last-block-done: tail processing ----
    __syncthreads();
    if (t == 0) {
        __threadfence();
        isLast = (atomicAdd(&g_done, 1) == NBLK - 1);
    }
    __syncthreads();
    if (!isLast) return;
    __threadfence();    // acquire: see all blocks' g_list/g_gm writes

    // reset g_best for next replay (all blocks have consumed it)
    for (int z = t; z < BSN; z += 256) g_best[z] = 0ull;

    // exact logsumexp penalty for worklisted columns (empty in
    // expectation for random tokens; exact for any input)
    const int n = g_nlist;
    float total = 0.0f;

    for (int wk = 0; wk < n; wk++) {
        const int bs = g_list[wk];
        const int bb = bs / S;
        const int s  = bs % S;
        const float m = g_gm[bs];

        const float* p = pred + (size_t)bb * V * S + s;

        float d = 0.0f;
        for (int v = t; v < V; v += 256)
            d += __expf(p[(size_t)v * S] - m);

        red[t] = d;
        __syncthreads();
        for (int st = 128; st > 0; st >>= 1) {
            if (t < st) red[t] += red[t + st];
            __syncthreads();
        }

        if (t == 0) {
            float D  = red[0];              // >= 1 (max term included)
            float lp = -logf(D);            // log_softmax at the argmax
            float pr = __expf(lp);
            float om = fmaxf(1.0f - pr, 1e-20f);
            total += -logf(om);
        }
        __syncthreads();
    }

    if (t == 0) {
        out[0] = total / (float)B;
        g_done = 0;                         // reset for next replay
    }
}

// ================================================================
extern "C" void kernel_launch(void* const* d_in, const int* in_sizes, int n_in,
                              void* d_out, int out_size)
{
    const float* pred = (const float*)d_in[0];

    dim3 g1(NC, B);
    k_argmax<<<g1, 128>>>(pred);

    dim3 g2(MSPL, B);
    k_masklse<<<g2, 256>>>(pred, (float*)d_out);
}